// round 15
// baseline (speedup 1.0000x reference)
#include <cuda_runtime.h>
#include <cuda_bf16.h>
#include <mma.h>
#include <math.h>

using namespace nvcuda;

#define BGRAPH 64
#define NNODE  1024
#define FDIM   128
#define NUM    (BGRAPH*NNODE)
#define NE     2097152
#define KSEL   4
#define BLDM   136   /* padded B leading dim: 272B stride, 16B-aligned, ~conflict-free */

__device__ float d_xn  [NUM*FDIM];
__device__ float d_hf  [NUM*FDIM];
__device__ float d_hs  [NUM*FDIM];
__device__ float d_feat[NUM*FDIM];
__device__ float d_stru[NUM*FDIM];
__device__ float d_gate[NUM*FDIM];
__device__ int   d_topk[NUM*KSEL];
__device__ int   d_cand[NUM*8];
__device__ int   d_cntf[NUM];
__device__ int   d_cnts[NUM];
__device__ int   d_offf[NUM];
__device__ int   d_offs[NUM];
__device__ int   d_fillf[NUM];
__device__ int   d_fills[NUM];
__device__ float d_dinvf[NUM];
__device__ float d_dinvs[NUM];
__device__ int   d_csrf[NUM*KSEL];
__device__ int   d_csrs[NE];
__device__ __align__(16) __nv_bfloat16 d_xa[NUM*FDIM];
__device__ __align__(16) __nv_bfloat16 d_xb[NUM*FDIM];
__device__ __align__(16) __nv_bfloat16 d_ya[NUM*FDIM];
__device__ __align__(16) __nv_bfloat16 d_yb[NUM*FDIM];
__device__ __align__(16) __nv_bfloat16 d_fa[NUM*FDIM];
__device__ __align__(16) __nv_bfloat16 d_fb[NUM*FDIM];
__device__ __align__(16) __nv_bfloat16 d_sa[NUM*FDIM];
__device__ __align__(16) __nv_bfloat16 d_sb[NUM*FDIM];

typedef unsigned long long ull;

__device__ __forceinline__ float warp_sum(float v) {
#pragma unroll
    for (int o = 16; o > 0; o >>= 1) v += __shfl_xor_sync(0xffffffffu, v, o);
    return v;
}

__device__ __forceinline__ void ins4(ull& k0, ull& k1, ull& k2, ull& k3, ull c) {
    if (c < k3) {
        k3 = c;
        if (k3 < k2) { ull t = k2; k2 = k3; k3 = t; }
        if (k2 < k1) { ull t = k1; k1 = k2; k2 = t; }
        if (k1 < k0) { ull t = k0; k0 = k1; k1 = t; }
    }
}

__device__ __forceinline__ void split_store(__nv_bfloat16* pa, __nv_bfloat16* pb,
                                            int idx, float v) {
    __nv_bfloat16 a = __float2bfloat16(v);
    pa[idx] = a;
    pb[idx] = __float2bfloat16(v - __bfloat162float(a));
}

// 1) row-normalize x + emit bf16 split planes of xn (for topk) and raw x (for h-GEMM)
__global__ void knorm(const float* __restrict__ x) {
    int row = blockIdx.x, t = threadIdx.x;
    float v = x[row * FDIM + t];
    float ss = warp_sum(v * v);
    __shared__ float sh[4];
    if ((t & 31) == 0) sh[t >> 5] = ss;
    __syncthreads();
    float tot = sh[0] + sh[1] + sh[2] + sh[3];
    float den = fmaxf(sqrtf(tot), 1e-8f);
    float xv = v / den;
    int i = row * FDIM + t;
    d_xn[i] = xv;
    split_store(d_xa, d_xb, i, xv);
    split_store(d_ya, d_yb, i, v);
}

// 2) zero counters
__global__ void kinit() {
    int i = blockIdx.x * blockDim.x + threadIdx.x;
    if (i < NUM) { d_cntf[i] = 0; d_cnts[i] = 0; d_fillf[i] = 0; d_fills[i] = 0; }
}

// 3) structural in-degree
__global__ void kcnt_s(const int* __restrict__ ei) {
    int e = blockIdx.x * blockDim.x + threadIdx.x;
    if (e < NE) atomicAdd(&d_cnts[ei[NE + e]], 1);
}

// 4a) candidate generation (unchanged from R14)
__global__ void __launch_bounds__(256, 2) ktopk_wmma() {
    __shared__ __align__(16) __nv_bfloat16 Bs[128 * BLDM];
    __shared__ __align__(16) float scr[8][16 * 20];
    const int g = blockIdx.y;
    const int rcbase = blockIdx.x * 128;
    const int tid = threadIdx.x, w = tid >> 5, lane = tid & 31;
    const int rowstart = rcbase + w * 16;
    const __nv_bfloat16* xa = d_xa + (size_t)g * NNODE * FDIM;
    const __nv_bfloat16* xb = d_xb + (size_t)g * NNODE * FDIM;

    wmma::fragment<wmma::matrix_a, 16, 16, 16, __nv_bfloat16, wmma::row_major> a0[8];
#pragma unroll
    for (int kt = 0; kt < 8; kt++) {
        wmma::load_matrix_sync(a0[kt], xa + (size_t)rowstart * FDIM + kt * 16, FDIM);
    }

    ull tk0 = ~0ull, tk1 = ~0ull, tk2 = ~0ull, tk3 = ~0ull;

    for (int cc = 0; cc < 8; cc++) {
        for (int h = 0; h < 2; h++) {
            wmma::fragment<wmma::accumulator, 16, 16, 16, float> c[4];
#pragma unroll
            for (int ct = 0; ct < 4; ct++) wmma::fill_fragment(c[ct], 0.0f);

            for (int pb = 0; pb < 2; pb++) {
                __syncthreads();
                {
                    const uint4* src = (const uint4*)((pb ? xb : xa) + (size_t)cc * 128 * FDIM);
                    uint4* dst = (uint4*)Bs;
                    for (int i = tid; i < 2048; i += 256) {
                        int col = i >> 4, kk = i & 15;
                        dst[col * 17 + kk] = src[i];
                    }
                }
                __syncthreads();
                if (pb == 0) {
#pragma unroll
                    for (int kt = 0; kt < 8; kt++) {
                        wmma::fragment<wmma::matrix_a, 16, 16, 16, __nv_bfloat16, wmma::row_major> a1f;
                        wmma::load_matrix_sync(a1f, xb + (size_t)rowstart * FDIM + kt * 16, FDIM);
#pragma unroll
                        for (int ct = 0; ct < 4; ct++) {
                            wmma::fragment<wmma::matrix_b, 16, 16, 16, __nv_bfloat16, wmma::col_major> b;
                            wmma::load_matrix_sync(b, Bs + (h * 4 + ct) * 16 * BLDM + kt * 16, BLDM);
                            wmma::mma_sync(c[ct], a0[kt], b, c[ct]);
                            wmma::mma_sync(c[ct], a1f, b, c[ct]);
                        }
                    }
                } else {
#pragma unroll
                    for (int kt = 0; kt < 8; kt++) {
#pragma unroll
                        for (int ct = 0; ct < 4; ct++) {
                            wmma::fragment<wmma::matrix_b, 16, 16, 16, __nv_bfloat16, wmma::col_major> b;
                            wmma::load_matrix_sync(b, Bs + (h * 4 + ct) * 16 * BLDM + kt * 16, BLDM);
                            wmma::mma_sync(c[ct], a0[kt], b, c[ct]);
                        }
                    }
                }
            }

#pragma unroll
            for (int ct = 0; ct < 4; ct++) {
                wmma::store_matrix_sync(&scr[w][0], c[ct], 20, wmma::mem_row_major);
                __syncwarp();
                int r = lane & 15, half = lane >> 4;
                int colbase = cc * 128 + (h * 4 + ct) * 16 + half * 8;
#pragma unroll
                for (int q = 0; q < 8; q++) {
                    float s = scr[w][r * 20 + half * 8 + q];
                    float dval = 1.0f - s;
                    unsigned u = __float_as_uint(dval);
                    u = (u & 0x80000000u) ? ~u : (u | 0x80000000u);
                    ull key = (((ull)(~u)) << 10) | (ull)(colbase + q);
                    ins4(tk0, tk1, tk2, tk3, key);
                }
                __syncwarp();
            }
        }
    }

    {
        int r = lane & 15, half = lane >> 4;
        int grow = g * NNODE + rowstart + r;
        ull ks[4] = {tk0, tk1, tk2, tk3};
#pragma unroll
        for (int q = 0; q < 4; q++) {
            d_cand[grow * 8 + half * 4 + q] = g * NNODE + (int)(ks[q] & 1023ull);
        }
    }
}

// 4b) exact fp32 rescore of the 8 candidates -> final top-4 (one warp per row)
__global__ void krescore() {
    int d = (blockIdx.x * blockDim.x + threadIdx.x) >> 5;
    int lane = threadIdx.x & 31;
    const float4* xn4 = (const float4*)d_xn;
    float4 xr = xn4[d * 32 + lane];
    ull k0 = ~0ull, k1 = ~0ull, k2 = ~0ull, k3 = ~0ull;
#pragma unroll
    for (int q = 0; q < 8; q++) {
        int cand = d_cand[d * 8 + q];
        float4 y = xn4[cand * 32 + lane];
        float dot = warp_sum(xr.x * y.x + xr.y * y.y + xr.z * y.z + xr.w * y.w);
        float dval = 1.0f - dot;
        unsigned u = __float_as_uint(dval);
        u = (u & 0x80000000u) ? ~u : (u | 0x80000000u);
        ull key = (((ull)(~u)) << 10) | (ull)(cand & 1023);
        ins4(k0, k1, k2, k3, key);
    }
    if (lane == 0) {
        int gbase = d & ~(NNODE - 1);
        ull ks[4] = {k0, k1, k2, k3};
#pragma unroll
        for (int q = 0; q < 4; q++) {
            int j = (int)(ks[q] & 1023ull);
            int dg = gbase + j;
            d_topk[d * 4 + q] = dg;
            atomicAdd(&d_cntf[dg], 1);
        }
    }
}

// 5) exclusive scans (block 0 = feature counts, block 1 = structural)
__global__ void kscan() {
    int which = blockIdx.x;
    const int* cnt = which ? d_cnts : d_cntf;
    int* off = which ? d_offs : d_offf;
    __shared__ int sh[1024];
    int t = threadIdx.x;
    int base = t * 64;
    int sum = 0;
    for (int i = 0; i < 64; i++) sum += cnt[base + i];
    sh[t] = sum;
    __syncthreads();
    for (int o = 1; o < 1024; o <<= 1) {
        int v = (t >= o) ? sh[t - o] : 0;
        __syncthreads();
        sh[t] += v;
        __syncthreads();
    }
    int run = sh[t] - sum;
    for (int i = 0; i < 64; i++) { int c = cnt[base + i]; off[base + i] = run; run += c; }
}

// 6) dinv = rsqrt(deg) incl. self-loop
__global__ void kdinv() {
    int i = blockIdx.x * blockDim.x + threadIdx.x;
    if (i < NUM) {
        d_dinvf[i] = rsqrtf((float)(d_cntf[i] + 1));
        d_dinvs[i] = rsqrtf((float)(d_cnts[i] + 1));
    }
}

// 7) CSR fill
__global__ void kfill_f() {
    int e = blockIdx.x * blockDim.x + threadIdx.x;
    if (e < NUM * KSEL) {
        int srcn = e >> 2;
        int dg = d_topk[e];
        int pos = d_offf[dg] + atomicAdd(&d_fillf[dg], 1);
        d_csrf[pos] = srcn;
    }
}
__global__ void kfill_s(const int* __restrict__ ei) {
    int e = blockIdx.x * blockDim.x + threadIdx.x;
    if (e < NE) {
        int s = ei[e], dg = ei[NE + e];
        int pos = d_offs[dg] + atomicAdd(&d_fills[dg], 1);
        d_csrs[pos] = s;
    }
}

// 8) h = x @ W via WMMA 2-plane split (grid.y: 0=feat, 1=stru). 128 rows/CTA.
__global__ void __launch_bounds__(256, 2) kgemm_h_wmma(const float* __restrict__ Wf,
                                                       const float* __restrict__ Wst) {
    __shared__ __align__(16) __nv_bfloat16 Ws[128 * BLDM];
    const float* W = blockIdx.y ? Wst : Wf;
    float* out = blockIdx.y ? d_hs : d_hf;
    const int tid = threadIdx.x, w = tid >> 5;
    const int rowstart = blockIdx.x * 128 + w * 16;

    wmma::fragment<wmma::accumulator, 16, 16, 16, float> c[8];
#pragma unroll
    for (int ct = 0; ct < 8; ct++) wmma::fill_fragment(c[ct], 0.0f);

    for (int pb = 0; pb < 2; pb++) {
        __syncthreads();
        for (int i = tid; i < 16384; i += 256) {
            int k = i >> 7, j = i & 127;
            float wv = W[i];
            __nv_bfloat16 a = __float2bfloat16(wv);
            Ws[j * BLDM + k] = pb ? __float2bfloat16(wv - __bfloat162float(a)) : a;
        }
        __syncthreads();
#pragma unroll
        for (int kt = 0; kt < 8; kt++) {
            wmma::fragment<wmma::matrix_a, 16, 16, 16, __nv_bfloat16, wmma::row_major> a0;
            wmma::load_matrix_sync(a0, d_ya + (size_t)rowstart * FDIM + kt * 16, FDIM);
            if (pb == 0) {
                wmma::fragment<wmma::matrix_a, 16, 16, 16, __nv_bfloat16, wmma::row_major> a1;
                wmma::load_matrix_sync(a1, d_yb + (size_t)rowstart * FDIM + kt * 16, FDIM);
#pragma unroll
                for (int ct = 0; ct < 8; ct++) {
                    wmma::fragment<wmma::matrix_b, 16, 16, 16, __nv_bfloat16, wmma::col_major> b;
                    wmma::load_matrix_sync(b, Ws + ct * 16 * BLDM + kt * 16, BLDM);
                    wmma::mma_sync(c[ct], a0, b, c[ct]);
                    wmma::mma_sync(c[ct], a1, b, c[ct]);
                }
            } else {
#pragma unroll
                for (int ct = 0; ct < 8; ct++) {
                    wmma::fragment<wmma::matrix_b, 16, 16, 16, __nv_bfloat16, wmma::col_major> b;
                    wmma::load_matrix_sync(b, Ws + ct * 16 * BLDM + kt * 16, BLDM);
                    wmma::mma_sync(c[ct], a0, b, c[ct]);
                }
            }
        }
    }
#pragma unroll
    for (int ct = 0; ct < 8; ct++) {
        wmma::store_matrix_sync(out + (size_t)rowstart * FDIM + ct * 16, c[ct], FDIM,
                                wmma::mem_row_major);
    }
}

// 9) GCN aggregate + bias + relu + layernorm; epilogue writes fp32 + bf16 split planes
__global__ void kagg(int which, const float* __restrict__ bias,
                     const float* __restrict__ gamma, const float* __restrict__ beta) {
    int d = (blockIdx.x * blockDim.x + threadIdx.x) >> 5;
    int lane = threadIdx.x & 31;
    const int* off = which ? d_offs : d_offf;
    const int* cnt = which ? d_cnts : d_cntf;
    const int* csr = which ? d_csrs : d_csrf;
    const float* dinv = which ? d_dinvs : d_dinvf;
    const float4* h4 = which ? (const float4*)d_hs : (const float4*)d_hf;
    float* outp = which ? d_stru : d_feat;
    __nv_bfloat16* pa = which ? d_sa : d_fa;
    __nv_bfloat16* pbuf = which ? d_sb : d_fb;

    int st = off[d], n = cnt[d];
    float dd = dinv[d];
    float ax = 0.f, ay = 0.f, az = 0.f, aw = 0.f;
    int e = 0;
    for (; e + 4 <= n; e += 4) {
        int s0 = csr[st+e], s1 = csr[st+e+1], s2 = csr[st+e+2], s3 = csr[st+e+3];
        float w0 = dinv[s0]*dd, w1 = dinv[s1]*dd, w2 = dinv[s2]*dd, w3 = dinv[s3]*dd;
        float4 v0 = h4[s0*32+lane], v1 = h4[s1*32+lane];
        float4 v2 = h4[s2*32+lane], v3 = h4[s3*32+lane];
        ax += v0.x*w0 + v1.x*w1 + v2.x*w2 + v3.x*w3;
        ay += v0.y*w0 + v1.y*w1 + v2.y*w2 + v3.y*w3;
        az += v0.z*w0 + v1.z*w1 + v2.z*w2 + v3.z*w3;
        aw += v0.w*w0 + v1.w*w1 + v2.w*w2 + v3.w*w3;
    }
    for (; e < n; e++) {
        int s = csr[st + e];
        float wg = dinv[s] * dd;
        float4 v = h4[s*32+lane];
        ax += v.x*wg; ay += v.y*wg; az += v.z*wg; aw += v.w*wg;
    }
    {
        float4 v = h4[d*32+lane];
        float wg = dd * dd;
        ax += v.x*wg; ay += v.y*wg; az += v.z*wg; aw += v.w*wg;
    }
    float4 b4 = ((const float4*)bias)[lane];
    ax = fmaxf(ax + b4.x, 0.f); ay = fmaxf(ay + b4.y, 0.f);
    az = fmaxf(az + b4.z, 0.f); aw = fmaxf(aw + b4.w, 0.f);
    float mean = warp_sum(ax + ay + az + aw) * (1.0f / 128.0f);
    float dx = ax - mean, dy = ay - mean, dz = az - mean, dw = aw - mean;
    float var = warp_sum(dx*dx + dy*dy + dz*dz + dw*dw) * (1.0f / 128.0f);
    float rs = rsqrtf(var + 1e-5f);
    float4 g4 = ((const float4*)gamma)[lane], e4 = ((const float4*)beta)[lane];
    float4 o = {dx*rs*g4.x + e4.x, dy*rs*g4.y + e4.y,
                dz*rs*g4.z + e4.z, dw*rs*g4.w + e4.w};
    ((float4*)outp)[d*32+lane] = o;
    int ib = d * FDIM + lane * 4;
    split_store(pa, pbuf, ib + 0, o.x);
    split_store(pa, pbuf, ib + 1, o.y);
    split_store(pa, pbuf, ib + 2, o.z);
    split_store(pa, pbuf, ib + 3, o.w);
}

// 10) gate = sigmoid([feat|stru] @ W_gate + b_gate) via WMMA 2-plane split
__global__ void __launch_bounds__(256, 2) kgemm_gate_wmma(const float* __restrict__ Wg,
                                                          const float* __restrict__ bg) {
    __shared__ __align__(16) __nv_bfloat16 Ws[128 * BLDM];
    __shared__ __align__(16) float scr[8][16 * 20];
    const int tid = threadIdx.x, w = tid >> 5, lane = tid & 31;
    const int rowstart = blockIdx.x * 128 + w * 16;

    wmma::fragment<wmma::accumulator, 16, 16, 16, float> c[8];
#pragma unroll
    for (int ct = 0; ct < 8; ct++) wmma::fill_fragment(c[ct], 0.0f);

    for (int pb = 0; pb < 2; pb++) {
        for (int kc = 0; kc < 2; kc++) {
            __syncthreads();
            for (int i = tid; i < 16384; i += 256) {
                int k = i >> 7, j = i & 127;
                float wv = Wg[(kc * 128 + k) * FDIM + j];
                __nv_bfloat16 a = __float2bfloat16(wv);
                Ws[j * BLDM + k] = pb ? __float2bfloat16(wv - __bfloat162float(a)) : a;
            }
            __syncthreads();
            const __nv_bfloat16* Aa = kc ? d_sa : d_fa;
            const __nv_bfloat16* Ab = kc ? d_sb : d_fb;
#pragma unroll
            for (int kt = 0; kt < 8; kt++) {
                wmma::fragment<wmma::matrix_a, 16, 16, 16, __nv_bfloat16, wmma::row_major> a0;
                wmma::load_matrix_sync(a0, Aa + (size_t)rowstart * FDIM + kt * 16, FDIM);
                if (pb == 0) {
                    wmma::fragment<wmma::matrix_a, 16, 16, 16, __nv_bfloat16, wmma::row_major> a1;
                    wmma::load_matrix_sync(a1, Ab + (size_t)rowstart * FDIM + kt * 16, FDIM);
#pragma unroll
                    for (int ct = 0; ct < 8; ct++) {
                        wmma::fragment<wmma::matrix_b, 16, 16, 16, __nv_bfloat16, wmma::col_major> b;
                        wmma::load_matrix_sync(b, Ws + ct * 16 * BLDM + kt * 16, BLDM);
                        wmma::mma_sync(c[ct], a0, b, c[ct]);
                        wmma::mma_sync(c[ct], a1, b, c[ct]);
                    }
                } else {
#pragma unroll
                    for (int ct = 0; ct < 8; ct++) {
                        wmma::fragment<wmma::matrix_b, 16, 16, 16, __nv_bfloat16, wmma::col_major> b;
                        wmma::load_matrix_sync(b, Ws + ct * 16 * BLDM + kt * 16, BLDM);
                        wmma::mma_sync(c[ct], a0, b, c[ct]);
                    }
                }
            }
        }
    }
#pragma unroll
    for (int ct = 0; ct < 8; ct++) {
        wmma::store_matrix_sync(&scr[w][0], c[ct], 20, wmma::mem_row_major);
        __syncwarp();
        int r = lane & 15, half = lane >> 4;
        int col = ct * 16 + half * 8;
        int row = rowstart + r;
#pragma unroll
        for (int q = 0; q < 8; q++) {
            float z = scr[w][r * 20 + half * 8 + q] + bg[col + q];
            d_gate[row * FDIM + col + q] = 1.0f / (1.0f + expf(-z));
        }
        __syncwarp();
    }
}

// 11) fuse + layernorm + residual
__global__ void kfinal(const float* __restrict__ x, const float* __restrict__ gamma,
                       const float* __restrict__ beta, float* __restrict__ out) {
    int d = (blockIdx.x * blockDim.x + threadIdx.x) >> 5;
    int lane = threadIdx.x & 31;
    float4 f = ((const float4*)d_feat)[d*32+lane];
    float4 s = ((const float4*)d_stru)[d*32+lane];
    float4 g = ((const float4*)d_gate)[d*32+lane];
    float4 xv = ((const float4*)x)[d*32+lane];
    float fx = g.x*f.x + (1.f-g.x)*s.x;
    float fy = g.y*f.y + (1.f-g.y)*s.y;
    float fz = g.z*f.z + (1.f-g.z)*s.z;
    float fw = g.w*f.w + (1.f-g.w)*s.w;
    float mean = warp_sum(fx + fy + fz + fw) * (1.0f / 128.0f);
    float dx = fx-mean, dy = fy-mean, dz = fz-mean, dw = fw-mean;
    float var = warp_sum(dx*dx + dy*dy + dz*dz + dw*dw) * (1.0f / 128.0f);
    float rs = rsqrtf(var + 1e-5f);
    float4 g4 = ((const float4*)gamma)[lane], b4 = ((const float4*)beta)[lane];
    float4 o = {dx*rs*g4.x + b4.x + xv.x, dy*rs*g4.y + b4.y + xv.y,
                dz*rs*g4.z + b4.z + xv.z, dw*rs*g4.w + b4.w + xv.w};
    ((float4*)out)[d*32+lane] = o;
}

extern "C" void kernel_launch(void* const* d_in, const int* in_sizes, int n_in,
                              void* d_out, int out_size) {
    const float* x      = (const float*)d_in[0];
    const int*   ei     = (const int*)  d_in[1];
    const float* W_feat = (const float*)d_in[2];
    const float* b_feat = (const float*)d_in[3];
    const float* W_stru = (const float*)d_in[4];
    const float* b_stru = (const float*)d_in[5];
    const float* W_gate = (const float*)d_in[6];
    const float* b_gate = (const float*)d_in[7];
    const float* g_feat = (const float*)d_in[8];
    const float* be_feat= (const float*)d_in[9];
    const float* g_stru = (const float*)d_in[10];
    const float* be_stru= (const float*)d_in[11];
    const float* g_fus  = (const float*)d_in[12];
    const float* be_fus = (const float*)d_in[13];
    float* out = (float*)d_out;

    knorm<<<NUM, 128>>>(x);
    kinit<<<NUM / 256, 256>>>();
    kcnt_s<<<NE / 256, 256>>>(ei);
    ktopk_wmma<<<dim3(8, 64), 256>>>();
    krescore<<<(NUM * 32) / 256, 256>>>();
    kgemm_h_wmma<<<dim3(NUM / 128, 2), 256>>>(W_feat, W_stru);
    kscan<<<2, 1024>>>();
    kdinv<<<NUM / 256, 256>>>();
    kfill_f<<<(NUM * KSEL) / 256, 256>>>();
    kfill_s<<<NE / 256, 256>>>(ei);
    kagg<<<(NUM * 32) / 256, 256>>>(0, b_feat, g_feat, be_feat);
    kagg<<<(NUM * 32) / 256, 256>>>(1, b_stru, g_stru, be_stru);
    kgemm_gate_wmma<<<NUM / 128, 256>>>(W_gate, b_gate);
    kfinal<<<(NUM * 32) / 256, 256>>>(x, g_fus, be_fus, out);
}